// round 1
// baseline (speedup 1.0000x reference)
#include <cuda_runtime.h>

// Problem constants
#define NH 16
#define NB 2
#define NS 2048
#define ND 1024
#define HD 64
#define NM (NS*NB)   // 4096 rows

// Scratch (device globals: allocation-free)
__device__ float g_q[(size_t)NH*NB*NS*HD];   // [h][b][s][dk]
__device__ float g_k[(size_t)NH*NB*NS*HD];
__device__ float g_v[(size_t)NH*NB*NS*HD];
__device__ float g_ctx[(size_t)NM*ND];       // [s*B+b][dmodel]

__device__ __forceinline__ float f4get(const float4 v, int j) {
    return j == 0 ? v.x : (j == 1 ? v.y : (j == 2 ? v.z : v.w));
}

// ---------------------------------------------------------------------------
// GEMM: dst = A @ W^T + bias.   A:[4096,1024] rm, W:[1024,1024] rm (torch Linear)
// MODE 0: dst[m*1024 + n]  (row-major)
// MODE 1: scatter to [h][b][s][dk]:  dst[(((n/64)*NB + m%2)*NS + m/2)*64 + n%64]
// Tile 128x128x8, 256 threads, 8x8 per thread (split 4+4 fragments).
// ---------------------------------------------------------------------------
template<int MODE>
__global__ __launch_bounds__(256, 2) void sgemm_bias(
    const float* __restrict__ A, const float* __restrict__ W,
    const float* __restrict__ bias, float* __restrict__ dst)
{
    __shared__ float As[8][128];
    __shared__ float Bs[8][128];
    const int K = ND;
    const int tid = threadIdx.x;
    const int tx = tid & 15, ty = tid >> 4;
    const int bx = blockIdx.x, by = blockIdx.y;
    const float* Ab = A + (size_t)by * 128 * K;
    const float* Wb = W + (size_t)bx * 128 * K;
    const int lrow = tid >> 1;
    const int lcol = (tid & 1) * 4;

    float acc[8][8];
    #pragma unroll
    for (int i = 0; i < 8; i++)
        #pragma unroll
        for (int j = 0; j < 8; j++) acc[i][j] = 0.f;

    for (int k0 = 0; k0 < K; k0 += 8) {
        float4 av = *(const float4*)(Ab + (size_t)lrow * K + k0 + lcol);
        float4 wv = *(const float4*)(Wb + (size_t)lrow * K + k0 + lcol);
        As[lcol + 0][lrow] = av.x; As[lcol + 1][lrow] = av.y;
        As[lcol + 2][lrow] = av.z; As[lcol + 3][lrow] = av.w;
        Bs[lcol + 0][lrow] = wv.x; Bs[lcol + 1][lrow] = wv.y;
        Bs[lcol + 2][lrow] = wv.z; Bs[lcol + 3][lrow] = wv.w;
        __syncthreads();
        #pragma unroll
        for (int kk = 0; kk < 8; kk++) {
            float a[8], b[8];
            *(float4*)&a[0] = *(const float4*)&As[kk][ty * 4];
            *(float4*)&a[4] = *(const float4*)&As[kk][64 + ty * 4];
            *(float4*)&b[0] = *(const float4*)&Bs[kk][tx * 4];
            *(float4*)&b[4] = *(const float4*)&Bs[kk][64 + tx * 4];
            #pragma unroll
            for (int i = 0; i < 8; i++)
                #pragma unroll
                for (int j = 0; j < 8; j++)
                    acc[i][j] = fmaf(a[i], b[j], acc[i][j]);
        }
        __syncthreads();
    }

    #pragma unroll
    for (int ig = 0; ig < 2; ig++) {
        #pragma unroll
        for (int ii = 0; ii < 4; ii++) {
            const int i = ig * 4 + ii;
            const int m = by * 128 + ig * 64 + ty * 4 + ii;
            #pragma unroll
            for (int jg = 0; jg < 2; jg++) {
                const int n = bx * 128 + jg * 64 + tx * 4;
                const int j = jg * 4;
                float4 r;
                r.x = acc[i][j + 0] + bias[n + 0];
                r.y = acc[i][j + 1] + bias[n + 1];
                r.z = acc[i][j + 2] + bias[n + 2];
                r.w = acc[i][j + 3] + bias[n + 3];
                if (MODE == 0) {
                    *(float4*)&dst[(size_t)m * ND + n] = r;
                } else {
                    const int h = n >> 6, dd = n & 63;
                    const int srow = m >> 1, bi = m & 1;
                    *(float4*)&dst[(((size_t)(h * NB + bi)) * NS + srow) * HD + dd] = r;
                }
            }
        }
    }
}

// ---------------------------------------------------------------------------
// Flash attention per (h,b): block = 128 q-rows, loop K/V in tiles of 64 rows.
// 256 threads as 16x16; each thread owns 8 rows x 4 cols.
// smem: Qs[128][68], KsT[64][68] (d-major), Vs[64][68], Ps[128][68]
// ---------------------------------------------------------------------------
#define AQ 128
#define AK 64
#define PW 68
#define ATTN_SMEM ((AQ*PW + AK*PW + AK*PW + AQ*PW) * 4)

__global__ __launch_bounds__(256) void attn_kernel()
{
    extern __shared__ float sm[];
    float* Qs  = sm;                    // AQ x PW  [qrow][d]
    float* KsT = Qs + AQ * PW;          // HD x PW  [d][krow]
    float* Vs  = KsT + AK * PW;         // AK x PW  [krow][d]
    float* Ps  = Vs + AK * PW;          // AQ x PW  [qrow][k]

    const int hb = blockIdx.y;          // h*NB + b
    const int qt = blockIdx.x;
    const float* Qb = g_q + (size_t)hb * NS * HD + (size_t)qt * AQ * HD;
    const float* Kb = g_k + (size_t)hb * NS * HD;
    const float* Vb = g_v + (size_t)hb * NS * HD;

    const int tid = threadIdx.x, tx = tid & 15, ty = tid >> 4;

    // Load Q tile: 128x64 floats, coalesced float4
    #pragma unroll
    for (int it = 0; it < 8; it++) {
        int idx = tid + it * 256;
        int r = idx >> 4;
        int c = (idx & 15) * 4;
        *(float4*)&Qs[r * PW + c] = *(const float4*)(Qb + r * HD + c);
    }

    float m_i[8], l_i[8], o[8][4];
    #pragma unroll
    for (int i = 0; i < 8; i++) {
        m_i[i] = -1e30f; l_i[i] = 0.f;
        #pragma unroll
        for (int j = 0; j < 4; j++) o[i][j] = 0.f;
    }

    for (int kt = 0; kt < NS / AK; kt++) {
        __syncthreads();   // prior PV reads of Vs/Ps done; also orders Q load on iter 0
        // Load K (transposed to d-major) and V tiles
        #pragma unroll
        for (int it = 0; it < 4; it++) {
            int idx = tid + it * 256;
            int r = idx >> 4;
            int c = (idx & 15) * 4;
            float4 kv = *(const float4*)(Kb + (size_t)(kt * AK + r) * HD + c);
            KsT[(c + 0) * PW + r] = kv.x;
            KsT[(c + 1) * PW + r] = kv.y;
            KsT[(c + 2) * PW + r] = kv.z;
            KsT[(c + 3) * PW + r] = kv.w;
            *(float4*)&Vs[r * PW + c] = *(const float4*)(Vb + (size_t)(kt * AK + r) * HD + c);
        }
        __syncthreads();

        // Scores: sc[i][j] = Q[row_i] . K[col_j]
        float sc[8][4];
        #pragma unroll
        for (int i = 0; i < 8; i++)
            #pragma unroll
            for (int j = 0; j < 4; j++) sc[i][j] = 0.f;

        #pragma unroll
        for (int d4 = 0; d4 < HD; d4 += 4) {
            float4 k0v = *(const float4*)&KsT[(d4 + 0) * PW + tx * 4];
            float4 k1v = *(const float4*)&KsT[(d4 + 1) * PW + tx * 4];
            float4 k2v = *(const float4*)&KsT[(d4 + 2) * PW + tx * 4];
            float4 k3v = *(const float4*)&KsT[(d4 + 3) * PW + tx * 4];
            #pragma unroll
            for (int i = 0; i < 8; i++) {
                float4 a4 = *(const float4*)&Qs[(ty * 8 + i) * PW + d4];
                #pragma unroll
                for (int j = 0; j < 4; j++) {
                    sc[i][j] = fmaf(a4.x, f4get(k0v, j),
                               fmaf(a4.y, f4get(k1v, j),
                               fmaf(a4.z, f4get(k2v, j),
                               fmaf(a4.w, f4get(k3v, j), sc[i][j]))));
                }
            }
        }

        // Online softmax (scale 1/sqrt(64)=0.125); row reductions across tx via shfl
        #pragma unroll
        for (int i = 0; i < 8; i++) {
            float tmax = -1e30f;
            #pragma unroll
            for (int j = 0; j < 4; j++) {
                sc[i][j] *= 0.125f;
                tmax = fmaxf(tmax, sc[i][j]);
            }
            tmax = fmaxf(tmax, __shfl_xor_sync(0xffffffffu, tmax, 8));
            tmax = fmaxf(tmax, __shfl_xor_sync(0xffffffffu, tmax, 4));
            tmax = fmaxf(tmax, __shfl_xor_sync(0xffffffffu, tmax, 2));
            tmax = fmaxf(tmax, __shfl_xor_sync(0xffffffffu, tmax, 1));
            float mn = fmaxf(m_i[i], tmax);
            float corr = __expf(m_i[i] - mn);
            m_i[i] = mn;
            float rs = 0.f;
            #pragma unroll
            for (int j = 0; j < 4; j++) {
                sc[i][j] = __expf(sc[i][j] - mn);
                rs += sc[i][j];
            }
            rs += __shfl_xor_sync(0xffffffffu, rs, 8);
            rs += __shfl_xor_sync(0xffffffffu, rs, 4);
            rs += __shfl_xor_sync(0xffffffffu, rs, 2);
            rs += __shfl_xor_sync(0xffffffffu, rs, 1);
            l_i[i] = l_i[i] * corr + rs;
            #pragma unroll
            for (int j = 0; j < 4; j++) o[i][j] *= corr;
            *(float4*)&Ps[(ty * 8 + i) * PW + tx * 4] =
                make_float4(sc[i][0], sc[i][1], sc[i][2], sc[i][3]);
        }
        __syncthreads();

        // O += P @ V
        #pragma unroll
        for (int k4 = 0; k4 < AK; k4 += 4) {
            float4 v0 = *(const float4*)&Vs[(k4 + 0) * PW + tx * 4];
            float4 v1 = *(const float4*)&Vs[(k4 + 1) * PW + tx * 4];
            float4 v2 = *(const float4*)&Vs[(k4 + 2) * PW + tx * 4];
            float4 v3 = *(const float4*)&Vs[(k4 + 3) * PW + tx * 4];
            #pragma unroll
            for (int i = 0; i < 8; i++) {
                float4 p4 = *(const float4*)&Ps[(ty * 8 + i) * PW + k4];
                #pragma unroll
                for (int j = 0; j < 4; j++) {
                    o[i][j] = fmaf(p4.x, f4get(v0, j),
                              fmaf(p4.y, f4get(v1, j),
                              fmaf(p4.z, f4get(v2, j),
                              fmaf(p4.w, f4get(v3, j), o[i][j]))));
                }
            }
        }
    }

    // Normalize and write to ctx [s*B+b][dmodel]
    const int h = hb >> 1, bi = hb & 1;
    #pragma unroll
    for (int i = 0; i < 8; i++) {
        float inv = 1.0f / l_i[i];
        int srow = qt * AQ + ty * 8 + i;
        float4 r = make_float4(o[i][0] * inv, o[i][1] * inv,
                               o[i][2] * inv, o[i][3] * inv);
        *(float4*)&g_ctx[((size_t)srow * NB + bi) * ND + h * HD + tx * 4] = r;
    }
}

// ---------------------------------------------------------------------------
extern "C" void kernel_launch(void* const* d_in, const int* in_sizes, int n_in,
                              void* d_out, int out_size)
{
    const float* query = (const float*)d_in[0];
    const float* key_  = (const float*)d_in[1];
    const float* value = (const float*)d_in[2];
    const float* Wq = (const float*)d_in[3];
    const float* bq = (const float*)d_in[4];
    const float* Wk = (const float*)d_in[5];
    const float* bk = (const float*)d_in[6];
    const float* Wv = (const float*)d_in[7];
    const float* bv = (const float*)d_in[8];
    const float* Wo = (const float*)d_in[9];
    const float* bo = (const float*)d_in[10];
    float* out = (float*)d_out;

    float *pq, *pk, *pv, *pctx;
    cudaGetSymbolAddress((void**)&pq, g_q);
    cudaGetSymbolAddress((void**)&pk, g_k);
    cudaGetSymbolAddress((void**)&pv, g_v);
    cudaGetSymbolAddress((void**)&pctx, g_ctx);

    cudaFuncSetAttribute(attn_kernel,
                         cudaFuncAttributeMaxDynamicSharedMemorySize, ATTN_SMEM);

    dim3 gemm_grid(ND / 128, NM / 128);   // (8, 32)
    sgemm_bias<1><<<gemm_grid, 256>>>(query, Wq, bq, pq);
    sgemm_bias<1><<<gemm_grid, 256>>>(key_,  Wk, bk, pk);
    sgemm_bias<1><<<gemm_grid, 256>>>(value, Wv, bv, pv);

    attn_kernel<<<dim3(NS / AQ, NH * NB), 256, ATTN_SMEM>>>();   // (16, 32)

    sgemm_bias<0><<<gemm_grid, 256>>>(pctx, Wo, bo, out);
}

// round 4
// speedup vs baseline: 1.1687x; 1.1687x over previous
#include <cuda_runtime.h>
#include <cuda_bf16.h>
#include <cstdint>

// Problem constants
#define NH 16
#define NB 2
#define NS 2048
#define ND 1024
#define HD 64
#define NM (NS*NB)   // 4096 rows

// Scratch (device globals: allocation-free)
__device__ float g_q[(size_t)NH*NB*NS*HD];   // [h][b][s][dk]
__device__ float g_k[(size_t)NH*NB*NS*HD];
__device__ float g_v[(size_t)NH*NB*NS*HD];
__device__ float g_ctx[(size_t)NM*ND];       // [s*B+b][dmodel]

// ===========================================================================
// Baseline-PTX helpers (NO sm_103a-gated instructions: mma.sync + ldmatrix only)
// ===========================================================================
__device__ __forceinline__ uint32_t smem_u32(const void* p) {
    uint32_t a;
    asm("{ .reg .u64 t; cvta.to.shared.u64 t, %1; cvt.u32.u64 %0, t; }"
        : "=r"(a) : "l"(p));
    return a;
}
__device__ __forceinline__ void ldsm_x4(uint32_t* r, uint32_t addr) {
    asm volatile("ldmatrix.sync.aligned.m8n8.x4.shared.b16 {%0,%1,%2,%3}, [%4];"
                 : "=r"(r[0]), "=r"(r[1]), "=r"(r[2]), "=r"(r[3]) : "r"(addr));
}
__device__ __forceinline__ void ldsm_x2(uint32_t* r, uint32_t addr) {
    asm volatile("ldmatrix.sync.aligned.m8n8.x2.shared.b16 {%0,%1}, [%2];"
                 : "=r"(r[0]), "=r"(r[1]) : "r"(addr));
}
__device__ __forceinline__ void mma_bf16(float* c, const uint32_t* a, const uint32_t* b) {
    asm volatile("mma.sync.aligned.m16n8k16.row.col.f32.bf16.bf16.f32 "
                 "{%0,%1,%2,%3}, {%4,%5,%6,%7}, {%8,%9}, {%0,%1,%2,%3};"
                 : "+f"(c[0]), "+f"(c[1]), "+f"(c[2]), "+f"(c[3])
                 : "r"(a[0]), "r"(a[1]), "r"(a[2]), "r"(a[3]),
                   "r"(b[0]), "r"(b[1]));
}
__device__ __forceinline__ uint32_t pk2(__nv_bfloat16 a, __nv_bfloat16 b) {
    return (uint32_t)__bfloat16_as_ushort(a) | ((uint32_t)__bfloat16_as_ushort(b) << 16);
}
__device__ __forceinline__ float f4get(const float4 v, int j) {
    return j == 0 ? v.x : (j == 1 ? v.y : (j == 2 ? v.z : v.w));
}
// Split a float into bf16 hi + bf16 lo (residual)
__device__ __forceinline__ void split2(float x, __nv_bfloat16& h, __nv_bfloat16& l) {
    h = __float2bfloat16_rn(x);
    l = __float2bfloat16_rn(x - __bfloat162float(h));
}

// ===========================================================================
// HMMA GEMM: dst = A @ W^T + bias   (3x bf16 split, fp32 accumulate)
// A:[4096,1024] rm, W:[1024,1024] rm.  CTA tile 128x128, K-step 32.
// 8 warps: warp_m = wid>>1 (32 rows), warp_n = wid&1 (64 cols).
// MODE 0: row-major out.  MODE 1: scatter to [h][b][s][dk].
// ===========================================================================
#define BM 128
#define BN 128
#define BK 32
#define LDT 40          // padded halves per smem row (80B: conflict-free ldmatrix)

template<int MODE>
__global__ __launch_bounds__(256, 1) void hmma_gemm(
    const float* __restrict__ A, const float* __restrict__ W,
    const float* __restrict__ bias, float* __restrict__ dst)
{
    __shared__ __nv_bfloat16 Ah[BM * LDT], Al[BM * LDT];
    __shared__ __nv_bfloat16 Bh[BN * LDT], Bl[BN * LDT];

    const int tid = threadIdx.x;
    const int wid = tid >> 5, lane = tid & 31;
    const int warp_m = wid >> 1, warp_n = wid & 1;
    const int m0 = blockIdx.y * BM, n0 = blockIdx.x * BN;

    const uint32_t sAh = smem_u32(Ah), sAl = smem_u32(Al);
    const uint32_t sBh = smem_u32(Bh), sBl = smem_u32(Bl);

    // Load mapping: row = tid>>1 (0..127), c0 = (tid&1)*16 (halves of 32-col slab)
    const int row = tid >> 1;
    const int c0 = (tid & 1) * 16;
    const float* Aptr = A + (size_t)(m0 + row) * ND + c0;
    const float* Wptr = W + (size_t)(n0 + row) * ND + c0;

    float acc[2][8][4];
    #pragma unroll
    for (int i = 0; i < 2; i++)
        #pragma unroll
        for (int j = 0; j < 8; j++)
            #pragma unroll
            for (int q = 0; q < 4; q++) acc[i][j][q] = 0.f;

    float4 abuf[4], bbuf[4];
    #pragma unroll
    for (int j = 0; j < 4; j++) {
        abuf[j] = *(const float4*)(Aptr + j * 4);
        bbuf[j] = *(const float4*)(Wptr + j * 4);
    }

    for (int ks = 0; ks < ND / BK; ks++) {
        // Convert current slab to bf16 hi/lo and store to smem
        #pragma unroll
        for (int j = 0; j < 4; j++) {
            const uint32_t off = (uint32_t)(row * LDT + c0 + j * 4) * 2;  // bytes
            __nv_bfloat16 h0, h1, h2, h3, l0, l1, l2, l3;
            split2(abuf[j].x, h0, l0); split2(abuf[j].y, h1, l1);
            split2(abuf[j].z, h2, l2); split2(abuf[j].w, h3, l3);
            *(uint2*)((char*)Ah + off) = make_uint2(pk2(h0, h1), pk2(h2, h3));
            *(uint2*)((char*)Al + off) = make_uint2(pk2(l0, l1), pk2(l2, l3));
            split2(bbuf[j].x, h0, l0); split2(bbuf[j].y, h1, l1);
            split2(bbuf[j].z, h2, l2); split2(bbuf[j].w, h3, l3);
            *(uint2*)((char*)Bh + off) = make_uint2(pk2(h0, h1), pk2(h2, h3));
            *(uint2*)((char*)Bl + off) = make_uint2(pk2(l0, l1), pk2(l2, l3));
        }
        __syncthreads();

        // Prefetch next slab (overlaps with MMA work below)
        if (ks + 1 < ND / BK) {
            const int k0 = (ks + 1) * BK;
            #pragma unroll
            for (int j = 0; j < 4; j++) {
                abuf[j] = *(const float4*)(Aptr + k0 + j * 4);
                bbuf[j] = *(const float4*)(Wptr + k0 + j * 4);
            }
        }

        // MMA over the two k16 halves of this slab
        #pragma unroll
        for (int kk = 0; kk < 2; kk++) {
            uint32_t ah[2][4], al[2][4];
            #pragma unroll
            for (int i = 0; i < 2; i++) {
                const uint32_t aoff = (uint32_t)(
                    (warp_m * 32 + i * 16 + (lane & 15)) * LDT
                    + kk * 16 + (lane >> 4) * 8) * 2;
                ldsm_x4(ah[i], sAh + aoff);
                ldsm_x4(al[i], sAl + aoff);
            }
            uint32_t bh[8][2], bl[8][2];
            #pragma unroll
            for (int j = 0; j < 8; j++) {
                const uint32_t boff = (uint32_t)(
                    (warp_n * 64 + j * 8 + (lane & 7)) * LDT
                    + kk * 16 + ((lane >> 3) & 1) * 8) * 2;
                ldsm_x2(bh[j], sBh + boff);
                ldsm_x2(bl[j], sBl + boff);
            }
            #pragma unroll
            for (int i = 0; i < 2; i++)
                #pragma unroll
                for (int j = 0; j < 8; j++) {
                    mma_bf16(acc[i][j], ah[i], bh[j]);   // hi*hi
                    mma_bf16(acc[i][j], ah[i], bl[j]);   // hi*lo
                    mma_bf16(acc[i][j], al[i], bh[j]);   // lo*hi
                }
        }
        __syncthreads();
    }

    // Epilogue: c-frag thread t holds rows (t/4, t/4+8), cols (t%4)*2, +1
    #pragma unroll
    for (int i = 0; i < 2; i++) {
        #pragma unroll
        for (int j = 0; j < 8; j++) {
            const int rbase = m0 + warp_m * 32 + i * 16 + (lane >> 2);
            const int cbase = n0 + warp_n * 64 + j * 8 + (lane & 3) * 2;
            const float b0 = bias[cbase], b1 = bias[cbase + 1];
            #pragma unroll
            for (int rr = 0; rr < 2; rr++) {
                const int m = rbase + rr * 8;
                float2 o = make_float2(acc[i][j][rr * 2 + 0] + b0,
                                       acc[i][j][rr * 2 + 1] + b1);
                if (MODE == 0) {
                    *(float2*)&dst[(size_t)m * ND + cbase] = o;
                } else {
                    const int h = cbase >> 6, dd = cbase & 63;
                    const int srow = m >> 1, bi = m & 1;
                    *(float2*)&dst[(((size_t)(h * NB + bi)) * NS + srow) * HD + dd] = o;
                }
            }
        }
    }
}

// ===========================================================================
// Flash attention per (h,b): unchanged (fp32, passing, ~at fp32 roofline)
// ===========================================================================
#define AQ 128
#define AK 64
#define PW 68
#define ATTN_SMEM ((AQ*PW + AK*PW + AK*PW + AQ*PW) * 4)

__global__ __launch_bounds__(256) void attn_kernel()
{
    extern __shared__ float sm[];
    float* Qs  = sm;
    float* KsT = Qs + AQ * PW;
    float* Vs  = KsT + AK * PW;
    float* Ps  = Vs + AK * PW;

    const int hb = blockIdx.y;
    const int qt = blockIdx.x;
    const float* Qb = g_q + (size_t)hb * NS * HD + (size_t)qt * AQ * HD;
    const float* Kb = g_k + (size_t)hb * NS * HD;
    const float* Vb = g_v + (size_t)hb * NS * HD;

    const int tid = threadIdx.x, tx = tid & 15, ty = tid >> 4;

    #pragma unroll
    for (int it = 0; it < 8; it++) {
        int idx = tid + it * 256;
        int r = idx >> 4;
        int c = (idx & 15) * 4;
        *(float4*)&Qs[r * PW + c] = *(const float4*)(Qb + r * HD + c);
    }

    float m_i[8], l_i[8], o[8][4];
    #pragma unroll
    for (int i = 0; i < 8; i++) {
        m_i[i] = -1e30f; l_i[i] = 0.f;
        #pragma unroll
        for (int j = 0; j < 4; j++) o[i][j] = 0.f;
    }

    for (int kt = 0; kt < NS / AK; kt++) {
        __syncthreads();
        #pragma unroll
        for (int it = 0; it < 4; it++) {
            int idx = tid + it * 256;
            int r = idx >> 4;
            int c = (idx & 15) * 4;
            float4 kv = *(const float4*)(Kb + (size_t)(kt * AK + r) * HD + c);
            KsT[(c + 0) * PW + r] = kv.x;
            KsT[(c + 1) * PW + r] = kv.y;
            KsT[(c + 2) * PW + r] = kv.z;
            KsT[(c + 3) * PW + r] = kv.w;
            *(float4*)&Vs[r * PW + c] = *(const float4*)(Vb + (size_t)(kt * AK + r) * HD + c);
        }
        __syncthreads();

        float sc[8][4];
        #pragma unroll
        for (int i = 0; i < 8; i++)
            #pragma unroll
            for (int j = 0; j < 4; j++) sc[i][j] = 0.f;

        #pragma unroll
        for (int d4 = 0; d4 < HD; d4 += 4) {
            float4 k0v = *(const float4*)&KsT[(d4 + 0) * PW + tx * 4];
            float4 k1v = *(const float4*)&KsT[(d4 + 1) * PW + tx * 4];
            float4 k2v = *(const float4*)&KsT[(d4 + 2) * PW + tx * 4];
            float4 k3v = *(const float4*)&KsT[(d4 + 3) * PW + tx * 4];
            #pragma unroll
            for (int i = 0; i < 8; i++) {
                float4 a4 = *(const float4*)&Qs[(ty * 8 + i) * PW + d4];
                #pragma unroll
                for (int j = 0; j < 4; j++) {
                    sc[i][j] = fmaf(a4.x, f4get(k0v, j),
                               fmaf(a4.y, f4get(k1v, j),
                               fmaf(a4.z, f4get(k2v, j),
                               fmaf(a4.w, f4get(k3v, j), sc[i][j]))));
                }
            }
        }

        #pragma unroll
        for (int i = 0; i < 8; i++) {
            float tmax = -1e30f;
            #pragma unroll
            for (int j = 0; j < 4; j++) {
                sc[i][j] *= 0.125f;
                tmax = fmaxf(tmax, sc[i][j]);
            }
            tmax = fmaxf(tmax, __shfl_xor_sync(0xffffffffu, tmax, 8));
            tmax = fmaxf(tmax, __shfl_xor_sync(0xffffffffu, tmax, 4));
            tmax = fmaxf(tmax, __shfl_xor_sync(0xffffffffu, tmax, 2));
            tmax = fmaxf(tmax, __shfl_xor_sync(0xffffffffu, tmax, 1));
            float mn = fmaxf(m_i[i], tmax);
            float corr = __expf(m_i[i] - mn);
            m_i[i] = mn;
            float rs = 0.f;
            #pragma unroll
            for (int j = 0; j < 4; j++) {
                sc[i][j] = __expf(sc[i][j] - mn);
                rs += sc[i][j];
            }
            rs += __shfl_xor_sync(0xffffffffu, rs, 8);
            rs += __shfl_xor_sync(0xffffffffu, rs, 4);
            rs += __shfl_xor_sync(0xffffffffu, rs, 2);
            rs += __shfl_xor_sync(0xffffffffu, rs, 1);
            l_i[i] = l_i[i] * corr + rs;
            #pragma unroll
            for (int j = 0; j < 4; j++) o[i][j] *= corr;
            *(float4*)&Ps[(ty * 8 + i) * PW + tx * 4] =
                make_float4(sc[i][0], sc[i][1], sc[i][2], sc[i][3]);
        }
        __syncthreads();

        #pragma unroll
        for (int k4 = 0; k4 < AK; k4 += 4) {
            float4 v0 = *(const float4*)&Vs[(k4 + 0) * PW + tx * 4];
            float4 v1 = *(const float4*)&Vs[(k4 + 1) * PW + tx * 4];
            float4 v2 = *(const float4*)&Vs[(k4 + 2) * PW + tx * 4];
            float4 v3 = *(const float4*)&Vs[(k4 + 3) * PW + tx * 4];
            #pragma unroll
            for (int i = 0; i < 8; i++) {
                float4 p4 = *(const float4*)&Ps[(ty * 8 + i) * PW + k4];
                #pragma unroll
                for (int j = 0; j < 4; j++) {
                    o[i][j] = fmaf(p4.x, f4get(v0, j),
                              fmaf(p4.y, f4get(v1, j),
                              fmaf(p4.z, f4get(v2, j),
                              fmaf(p4.w, f4get(v3, j), o[i][j]))));
                }
            }
        }
    }

    const int h = hb >> 1, bi = hb & 1;
    #pragma unroll
    for (int i = 0; i < 8; i++) {
        float inv = 1.0f / l_i[i];
        int srow = qt * AQ + ty * 8 + i;
        float4 r = make_float4(o[i][0] * inv, o[i][1] * inv,
                               o[i][2] * inv, o[i][3] * inv);
        *(float4*)&g_ctx[((size_t)srow * NB + bi) * ND + h * HD + tx * 4] = r;
    }
}

// ---------------------------------------------------------------------------
extern "C" void kernel_launch(void* const* d_in, const int* in_sizes, int n_in,
                              void* d_out, int out_size)
{
    const float* query = (const float*)d_in[0];
    const float* key_  = (const float*)d_in[1];
    const float* value = (const float*)d_in[2];
    const float* Wq = (const float*)d_in[3];
    const float* bq = (const float*)d_in[4];
    const float* Wk = (const float*)d_in[5];
    const float* bk = (const float*)d_in[6];
    const float* Wv = (const float*)d_in[7];
    const float* bv = (const float*)d_in[8];
    const float* Wo = (const float*)d_in[9];
    const float* bo = (const float*)d_in[10];
    float* out = (float*)d_out;

    float *pq, *pk, *pv, *pctx;
    cudaGetSymbolAddress((void**)&pq, g_q);
    cudaGetSymbolAddress((void**)&pk, g_k);
    cudaGetSymbolAddress((void**)&pv, g_v);
    cudaGetSymbolAddress((void**)&pctx, g_ctx);

    cudaFuncSetAttribute(attn_kernel,
                         cudaFuncAttributeMaxDynamicSharedMemorySize, ATTN_SMEM);

    dim3 gemm_grid(ND / BN, NM / BM);   // (8, 32)
    hmma_gemm<1><<<gemm_grid, 256>>>(query, Wq, bq, pq);
    hmma_gemm<1><<<gemm_grid, 256>>>(key_,  Wk, bk, pk);
    hmma_gemm<1><<<gemm_grid, 256>>>(value, Wv, bv, pv);

    attn_kernel<<<dim3(NS / AQ, NH * NB), 256, ATTN_SMEM>>>();   // (16, 32)

    hmma_gemm<0><<<gemm_grid, 256>>>(pctx, Wo, bo, out);
}

// round 8
// speedup vs baseline: 2.4890x; 2.1297x over previous
#include <cuda_runtime.h>
#include <cuda_bf16.h>
#include <cstdint>

// Problem constants
#define NH 16
#define NB 2
#define NS 2048
#define ND 1024
#define HD 64
#define NM (NS*NB)   // 4096 rows

// ---------------------------------------------------------------------------
// Scratch (device globals: allocation-free). Packed bf16 arrays as uint32.
// ---------------------------------------------------------------------------
__device__ uint32_t g_ash[(size_t)NM*ND/2];    // A split hi (reused per GEMM)
__device__ uint32_t g_asl[(size_t)NM*ND/2];
__device__ uint32_t g_bsh[(size_t)ND*ND/2];    // W split hi (reused per GEMM)
__device__ uint32_t g_bsl[(size_t)ND*ND/2];
__device__ uint32_t g_qh[(size_t)NH*NB*NS*HD/2];  // [h][b][s][dk/2]
__device__ uint32_t g_ql[(size_t)NH*NB*NS*HD/2];
__device__ uint32_t g_kh[(size_t)NH*NB*NS*HD/2];
__device__ uint32_t g_kl[(size_t)NH*NB*NS*HD/2];
__device__ uint32_t g_vh[(size_t)NH*NB*NS*HD/2];
__device__ uint32_t g_vl[(size_t)NH*NB*NS*HD/2];
__device__ float    g_ctx[(size_t)NM*ND];         // [s*B+b][dmodel] fp32

// ===========================================================================
// Baseline-PTX helpers (mma.sync + ldmatrix only; no sm_103a-gated features)
// ===========================================================================
__device__ __forceinline__ uint32_t smem_u32(const void* p) {
    uint32_t a;
    asm("{ .reg .u64 t; cvta.to.shared.u64 t, %1; cvt.u32.u64 %0, t; }"
        : "=r"(a) : "l"(p));
    return a;
}
__device__ __forceinline__ void ldsm_x4(uint32_t* r, uint32_t addr) {
    asm volatile("ldmatrix.sync.aligned.m8n8.x4.shared.b16 {%0,%1,%2,%3}, [%4];"
                 : "=r"(r[0]), "=r"(r[1]), "=r"(r[2]), "=r"(r[3]) : "r"(addr));
}
__device__ __forceinline__ void ldsm_x4_t(uint32_t* r, uint32_t addr) {
    asm volatile("ldmatrix.sync.aligned.m8n8.x4.trans.shared.b16 {%0,%1,%2,%3}, [%4];"
                 : "=r"(r[0]), "=r"(r[1]), "=r"(r[2]), "=r"(r[3]) : "r"(addr));
}
__device__ __forceinline__ void mma_bf16(float* c, const uint32_t* a,
                                         uint32_t b0, uint32_t b1) {
    asm volatile("mma.sync.aligned.m16n8k16.row.col.f32.bf16.bf16.f32 "
                 "{%0,%1,%2,%3}, {%4,%5,%6,%7}, {%8,%9}, {%0,%1,%2,%3};"
                 : "+f"(c[0]), "+f"(c[1]), "+f"(c[2]), "+f"(c[3])
                 : "r"(a[0]), "r"(a[1]), "r"(a[2]), "r"(a[3]),
                   "r"(b0), "r"(b1));
}
__device__ __forceinline__ uint32_t pk2(__nv_bfloat16 a, __nv_bfloat16 b) {
    return (uint32_t)__bfloat16_as_ushort(a) | ((uint32_t)__bfloat16_as_ushort(b) << 16);
}
__device__ __forceinline__ void split2(float x, __nv_bfloat16& h, __nv_bfloat16& l) {
    h = __float2bfloat16_rn(x);
    l = __float2bfloat16_rn(x - __bfloat162float(h));
}
__device__ __forceinline__ void split_pair(float x, float y, uint32_t& h, uint32_t& l) {
    __nv_bfloat16 hx, lx, hy, ly;
    split2(x, hx, lx); split2(y, hy, ly);
    h = pk2(hx, hy); l = pk2(lx, ly);
}

// ===========================================================================
// split_pack: fp32 -> packed bf16 hi/lo
// ===========================================================================
__global__ void split_pack(const float* __restrict__ src,
                           uint32_t* __restrict__ hi, uint32_t* __restrict__ lo,
                           int n2)
{
    int i = blockIdx.x * blockDim.x + threadIdx.x;
    const int stride = gridDim.x * blockDim.x;
    for (; i < n2; i += stride) {
        float2 v = ((const float2*)src)[i];
        uint32_t h, l;
        split_pair(v.x, v.y, h, l);
        hi[i] = h; lo[i] = l;
    }
}

// ===========================================================================
// HMMA GEMM on pre-split operands: dst = A @ W^T + bias (3-term split)
// CTA tile 128x128, K-step 32. 8 warps: warp_m=wid>>1 (32 rows), warp_n=wid&1.
// MODE 0: fp32 row-major out.  MODE 1: bf16 hi/lo scatter to [h][b][s][dk].
// ===========================================================================
#define BM 128
#define BN 128
#define BK 32
#define LDT 40   // padded halves per smem row (80B, conflict-free ldmatrix)

template<int MODE>
__global__ __launch_bounds__(256, 1) void hmma_gemm(
    const uint32_t* __restrict__ Ah2, const uint32_t* __restrict__ Al2,
    const uint32_t* __restrict__ Bh2, const uint32_t* __restrict__ Bl2,
    const float* __restrict__ bias, float* __restrict__ dst,
    uint32_t* __restrict__ dsth, uint32_t* __restrict__ dstl)
{
    __shared__ __nv_bfloat16 Ah[BM * LDT], Al[BM * LDT];
    __shared__ __nv_bfloat16 Bh[BN * LDT], Bl[BN * LDT];

    const int tid = threadIdx.x;
    const int wid = tid >> 5, lane = tid & 31;
    const int warp_m = wid >> 1, warp_n = wid & 1;
    const int m0 = blockIdx.y * BM, n0 = blockIdx.x * BN;

    const uint32_t sAh = smem_u32(Ah), sAl = smem_u32(Al);
    const uint32_t sBh = smem_u32(Bh), sBl = smem_u32(Bl);

    // Load mapping: row = tid>>1 (0..127), c0 = (tid&1)*16 halves
    const int row = tid >> 1;
    const int c0 = (tid & 1) * 16;
    const uint32_t* Ahp = Ah2 + (size_t)(m0 + row) * (ND/2) + (c0 >> 1);
    const uint32_t* Alp = Al2 + (size_t)(m0 + row) * (ND/2) + (c0 >> 1);
    const uint32_t* Bhp = Bh2 + (size_t)(n0 + row) * (ND/2) + (c0 >> 1);
    const uint32_t* Blp = Bl2 + (size_t)(n0 + row) * (ND/2) + (c0 >> 1);

    float acc[2][8][4];
    #pragma unroll
    for (int i = 0; i < 2; i++)
        #pragma unroll
        for (int j = 0; j < 8; j++)
            #pragma unroll
            for (int q = 0; q < 4; q++) acc[i][j][q] = 0.f;

    uint4 pa[2], pal[2], pb[2], pbl[2];
    #pragma unroll
    for (int j = 0; j < 2; j++) {
        pa[j]  = *(const uint4*)(Ahp + j * 4);
        pal[j] = *(const uint4*)(Alp + j * 4);
        pb[j]  = *(const uint4*)(Bhp + j * 4);
        pbl[j] = *(const uint4*)(Blp + j * 4);
    }

    for (int ks = 0; ks < ND / BK; ks++) {
        #pragma unroll
        for (int j = 0; j < 2; j++) {
            const int off = row * LDT + c0 + j * 8;
            *(uint4*)&Ah[off] = pa[j];
            *(uint4*)&Al[off] = pal[j];
            *(uint4*)&Bh[off] = pb[j];
            *(uint4*)&Bl[off] = pbl[j];
        }
        __syncthreads();

        if (ks + 1 < ND / BK) {
            const int k32 = (ks + 1) * (BK / 2);
            #pragma unroll
            for (int j = 0; j < 2; j++) {
                pa[j]  = *(const uint4*)(Ahp + k32 + j * 4);
                pal[j] = *(const uint4*)(Alp + k32 + j * 4);
                pb[j]  = *(const uint4*)(Bhp + k32 + j * 4);
                pbl[j] = *(const uint4*)(Blp + k32 + j * 4);
            }
        }

        #pragma unroll
        for (int kk = 0; kk < 2; kk++) {
            uint32_t ah[2][4], al[2][4];
            #pragma unroll
            for (int i = 0; i < 2; i++) {
                const uint32_t aoff = (uint32_t)(
                    (warp_m * 32 + i * 16 + (lane & 15)) * LDT
                    + kk * 16 + (lane >> 4) * 8) * 2;
                ldsm_x4(ah[i], sAh + aoff);
                ldsm_x4(al[i], sAl + aoff);
            }
            #pragma unroll
            for (int g = 0; g < 4; g++) {
                uint32_t bh[4], bl[4];
                const uint32_t boff = (uint32_t)(
                    (warp_n * 64 + g * 16 + (lane & 15)) * LDT
                    + kk * 16 + (lane >> 4) * 8) * 2;
                ldsm_x4(bh, sBh + boff);
                ldsm_x4(bl, sBl + boff);
                #pragma unroll
                for (int i = 0; i < 2; i++) {
                    // n-tile 2g: b = {r0, r2}; n-tile 2g+1: b = {r1, r3}
                    mma_bf16(acc[i][2*g],   ah[i], bh[0], bh[2]);
                    mma_bf16(acc[i][2*g],   ah[i], bl[0], bl[2]);
                    mma_bf16(acc[i][2*g],   al[i], bh[0], bh[2]);
                    mma_bf16(acc[i][2*g+1], ah[i], bh[1], bh[3]);
                    mma_bf16(acc[i][2*g+1], ah[i], bl[1], bl[3]);
                    mma_bf16(acc[i][2*g+1], al[i], bh[1], bh[3]);
                }
            }
        }
        __syncthreads();
    }

    // Epilogue
    #pragma unroll
    for (int i = 0; i < 2; i++) {
        #pragma unroll
        for (int j = 0; j < 8; j++) {
            const int rbase = m0 + warp_m * 32 + i * 16 + (lane >> 2);
            const int cbase = n0 + warp_n * 64 + j * 8 + (lane & 3) * 2;
            const float b0 = bias[cbase], b1 = bias[cbase + 1];
            #pragma unroll
            for (int rr = 0; rr < 2; rr++) {
                const int m = rbase + rr * 8;
                const float o0 = acc[i][j][rr * 2 + 0] + b0;
                const float o1 = acc[i][j][rr * 2 + 1] + b1;
                if (MODE == 0) {
                    *(float2*)&dst[(size_t)m * ND + cbase] = make_float2(o0, o1);
                } else {
                    const int h = cbase >> 6, dd = cbase & 63;
                    const int srow = m >> 1, bi = m & 1;
                    const size_t idx =
                        (((size_t)(h * NB + bi)) * NS + srow) * (HD/2) + (dd >> 1);
                    uint32_t ph, pl;
                    split_pair(o0, o1, ph, pl);
                    dsth[idx] = ph;
                    dstl[idx] = pl;
                }
            }
        }
    }
}

// ===========================================================================
// HMMA flash attention. Per (h,b): CTA = 128 q-rows, key tiles of 64.
// 8 warps, warp w owns q-rows [w*16, w*16+16).
// QK:  Qh*Kh + Qh*Kl + Ql*Kh  (fp32 accum)
// PV:  Ph*Vh + Ph*Vl + Pl*Vh  (P split at use; V frags via ldmatrix.trans)
// ===========================================================================
#define LDA 72   // padded halves per row (144B: conflict-free ldmatrix)
#define ATTN_SMEM ((128*LDA*2 + 64*LDA*4) * 2)   // bytes = 73728

__global__ __launch_bounds__(256, 1) void attn_hmma()
{
    extern __shared__ __nv_bfloat16 smA[];
    __nv_bfloat16* Qh = smA;
    __nv_bfloat16* Ql = Qh + 128 * LDA;
    __nv_bfloat16* Kh = Ql + 128 * LDA;
    __nv_bfloat16* Kl = Kh + 64 * LDA;
    __nv_bfloat16* Vh = Kl + 64 * LDA;
    __nv_bfloat16* Vl = Vh + 64 * LDA;
    const uint32_t sQh = smem_u32(Qh), sQl = smem_u32(Ql);
    const uint32_t sKh = smem_u32(Kh), sKl = smem_u32(Kl);
    const uint32_t sVh = smem_u32(Vh), sVl = smem_u32(Vl);

    const int hb = blockIdx.y, qt = blockIdx.x;
    const int tid = threadIdx.x, wid = tid >> 5, lane = tid & 31;

    const uint32_t* qhp = g_qh + ((size_t)hb * NS + (size_t)qt * 128) * (HD/2);
    const uint32_t* qlp = g_ql + ((size_t)hb * NS + (size_t)qt * 128) * (HD/2);
    const uint32_t* khp = g_kh + (size_t)hb * NS * (HD/2);
    const uint32_t* klp = g_kl + (size_t)hb * NS * (HD/2);
    const uint32_t* vhp = g_vh + (size_t)hb * NS * (HD/2);
    const uint32_t* vlp = g_vl + (size_t)hb * NS * (HD/2);

    // Load Q tile: 1024 16B-chunks per array
    #pragma unroll
    for (int i = 0; i < 4; i++) {
        const int c = tid + i * 256;
        const int r = c >> 3, cc = (c & 7) * 8;
        *(uint4*)&Qh[r * LDA + cc] = *(const uint4*)(qhp + r * (HD/2) + (c & 7) * 4);
        *(uint4*)&Ql[r * LDA + cc] = *(const uint4*)(qlp + r * (HD/2) + (c & 7) * 4);
    }

    // K/V tile prefetch regs: per array 2 chunks per thread
    uint4 pre[8];
    {
        #pragma unroll
        for (int it = 0; it < 2; it++) {
            const int c = tid + it * 256;
            const size_t gi = (size_t)(c >> 3) * (HD/2) + (c & 7) * 4;
            pre[it]     = *(const uint4*)(khp + gi);
            pre[2 + it] = *(const uint4*)(klp + gi);
            pre[4 + it] = *(const uint4*)(vhp + gi);
            pre[6 + it] = *(const uint4*)(vlp + gi);
        }
    }

    float o[8][4];
    #pragma unroll
    for (int j = 0; j < 8; j++)
        #pragma unroll
        for (int q = 0; q < 4; q++) o[j][q] = 0.f;
    float m0 = -1e30f, m1 = -1e30f, l0 = 0.f, l1 = 0.f;

    for (int kt = 0; kt < NS / 64; kt++) {
        __syncthreads();   // previous tile's smem reads complete
        #pragma unroll
        for (int it = 0; it < 2; it++) {
            const int c = tid + it * 256;
            const int r = c >> 3, cc = (c & 7) * 8;
            *(uint4*)&Kh[r * LDA + cc] = pre[it];
            *(uint4*)&Kl[r * LDA + cc] = pre[2 + it];
            *(uint4*)&Vh[r * LDA + cc] = pre[4 + it];
            *(uint4*)&Vl[r * LDA + cc] = pre[6 + it];
        }
        __syncthreads();
        if (kt + 1 < NS / 64) {
            #pragma unroll
            for (int it = 0; it < 2; it++) {
                const int c = tid + it * 256;
                const size_t gi = (size_t)((kt + 1) * 64 + (c >> 3)) * (HD/2) + (c & 7) * 4;
                pre[it]     = *(const uint4*)(khp + gi);
                pre[2 + it] = *(const uint4*)(klp + gi);
                pre[4 + it] = *(const uint4*)(vhp + gi);
                pre[6 + it] = *(const uint4*)(vlp + gi);
            }
        }

        // ---- QK^T: sc[j][*] over 8 key n8-tiles ----
        float sc[8][4];
        #pragma unroll
        for (int j = 0; j < 8; j++)
            #pragma unroll
            for (int q = 0; q < 4; q++) sc[j][q] = 0.f;

        #pragma unroll
        for (int kk = 0; kk < 4; kk++) {   // d chunks of 16
            uint32_t aqh[4], aql[4];
            const uint32_t aoff = (uint32_t)(
                (wid * 16 + (lane & 15)) * LDA + kk * 16 + (lane >> 4) * 8) * 2;
            ldsm_x4(aqh, sQh + aoff);
            ldsm_x4(aql, sQl + aoff);
            #pragma unroll
            for (int g = 0; g < 4; g++) {  // key n16 groups
                uint32_t bh[4], bl[4];
                const uint32_t boff = (uint32_t)(
                    (g * 16 + (lane & 15)) * LDA + kk * 16 + (lane >> 4) * 8) * 2;
                ldsm_x4(bh, sKh + boff);
                ldsm_x4(bl, sKl + boff);
                mma_bf16(sc[2*g],   aqh, bh[0], bh[2]);
                mma_bf16(sc[2*g],   aqh, bl[0], bl[2]);
                mma_bf16(sc[2*g],   aql, bh[0], bh[2]);
                mma_bf16(sc[2*g+1], aqh, bh[1], bh[3]);
                mma_bf16(sc[2*g+1], aqh, bl[1], bl[3]);
                mma_bf16(sc[2*g+1], aql, bh[1], bh[3]);
            }
        }

        // ---- online softmax (rows r0=lane>>2, r1=r0+8 within warp m16) ----
        float mx0 = -1e30f, mx1 = -1e30f;
        #pragma unroll
        for (int j = 0; j < 8; j++) {
            sc[j][0] *= 0.125f; sc[j][1] *= 0.125f;
            sc[j][2] *= 0.125f; sc[j][3] *= 0.125f;
            mx0 = fmaxf(mx0, fmaxf(sc[j][0], sc[j][1]));
            mx1 = fmaxf(mx1, fmaxf(sc[j][2], sc[j][3]));
        }
        mx0 = fmaxf(mx0, __shfl_xor_sync(0xffffffffu, mx0, 1));
        mx0 = fmaxf(mx0, __shfl_xor_sync(0xffffffffu, mx0, 2));
        mx1 = fmaxf(mx1, __shfl_xor_sync(0xffffffffu, mx1, 1));
        mx1 = fmaxf(mx1, __shfl_xor_sync(0xffffffffu, mx1, 2));
        const float nm0 = fmaxf(m0, mx0), nm1 = fmaxf(m1, mx1);
        const float cr0 = __expf(m0 - nm0), cr1 = __expf(m1 - nm1);
        m0 = nm0; m1 = nm1;
        float s0 = 0.f, s1 = 0.f;
        #pragma unroll
        for (int j = 0; j < 8; j++) {
            sc[j][0] = __expf(sc[j][0] - nm0); s0 += sc[j][0];
            sc[j][1] = __expf(sc[j][1] - nm0); s0 += sc[j][1];
            sc[j][2] = __expf(sc[j][2] - nm1); s1 += sc[j][2];
            sc[j][3] = __expf(sc[j][3] - nm1); s1 += sc[j][3];
        }
        s0 += __shfl_xor_sync(0xffffffffu, s0, 1);
        s0 += __shfl_xor_sync(0xffffffffu, s0, 2);
        s1 += __shfl_xor_sync(0xffffffffu, s1, 1);
        s1 += __shfl_xor_sync(0xffffffffu, s1, 2);
        l0 = l0 * cr0 + s0;
        l1 = l1 * cr1 + s1;
        #pragma unroll
        for (int j = 0; j < 8; j++) {
            o[j][0] *= cr0; o[j][1] *= cr0;
            o[j][2] *= cr1; o[j][3] *= cr1;
        }

        // ---- PV: O += P @ V ----
        #pragma unroll
        for (int kk = 0; kk < 4; kk++) {   // key chunks of 16 (= score tiles 2kk, 2kk+1)
            uint32_t ph[4], pl[4];
            split_pair(sc[2*kk][0],   sc[2*kk][1],   ph[0], pl[0]);
            split_pair(sc[2*kk][2],   sc[2*kk][3],   ph[1], pl[1]);
            split_pair(sc[2*kk+1][0], sc[2*kk+1][1], ph[2], pl[2]);
            split_pair(sc[2*kk+1][2], sc[2*kk+1][3], ph[3], pl[3]);
            #pragma unroll
            for (int g = 0; g < 4; g++) {  // d n16 groups
                uint32_t bvh[4], bvl[4];
                const uint32_t voff = (uint32_t)(
                    (kk * 16 + (lane & 7) + ((lane >> 3) & 1) * 8) * LDA
                    + g * 16 + (lane >> 4) * 8) * 2;
                ldsm_x4_t(bvh, sVh + voff);
                ldsm_x4_t(bvl, sVl + voff);
                // trans grouping: d-tile 2g: {r0, r1}; d-tile 2g+1: {r2, r3}
                mma_bf16(o[2*g],   ph, bvh[0], bvh[1]);
                mma_bf16(o[2*g],   ph, bvl[0], bvl[1]);
                mma_bf16(o[2*g],   pl, bvh[0], bvh[1]);
                mma_bf16(o[2*g+1], ph, bvh[2], bvh[3]);
                mma_bf16(o[2*g+1], ph, bvl[2], bvl[3]);
                mma_bf16(o[2*g+1], pl, bvh[2], bvh[3]);
            }
        }
    }

    // ---- epilogue: normalize, write ctx fp32 [s*B+b][dmodel] ----
    const int h = hb >> 1, bi = hb & 1;
    const float inv0 = 1.0f / l0, inv1 = 1.0f / l1;
    const int r0 = qt * 128 + wid * 16 + (lane >> 2);
    const int c2 = (lane & 3) * 2;
    #pragma unroll
    for (int j = 0; j < 8; j++) {
        const int d = j * 8 + c2;
        *(float2*)&g_ctx[((size_t)r0 * NB + bi) * ND + h * HD + d] =
            make_float2(o[j][0] * inv0, o[j][1] * inv0);
        *(float2*)&g_ctx[((size_t)(r0 + 8) * NB + bi) * ND + h * HD + d] =
            make_float2(o[j][2] * inv1, o[j][3] * inv1);
    }
}

// ---------------------------------------------------------------------------
extern "C" void kernel_launch(void* const* d_in, const int* in_sizes, int n_in,
                              void* d_out, int out_size)
{
    const float* query = (const float*)d_in[0];
    const float* key_  = (const float*)d_in[1];
    const float* value = (const float*)d_in[2];
    const float* Wq = (const float*)d_in[3];
    const float* bq = (const float*)d_in[4];
    const float* Wk = (const float*)d_in[5];
    const float* bk = (const float*)d_in[6];
    const float* Wv = (const float*)d_in[7];
    const float* bv = (const float*)d_in[8];
    const float* Wo = (const float*)d_in[9];
    const float* bo = (const float*)d_in[10];
    float* out = (float*)d_out;

    uint32_t *ash, *asl, *bsh, *bsl;
    uint32_t *qh, *ql, *kh, *kl, *vh, *vl;
    float* ctx;
    cudaGetSymbolAddress((void**)&ash, g_ash);
    cudaGetSymbolAddress((void**)&asl, g_asl);
    cudaGetSymbolAddress((void**)&bsh, g_bsh);
    cudaGetSymbolAddress((void**)&bsl, g_bsl);
    cudaGetSymbolAddress((void**)&qh, g_qh);
    cudaGetSymbolAddress((void**)&ql, g_ql);
    cudaGetSymbolAddress((void**)&kh, g_kh);
    cudaGetSymbolAddress((void**)&kl, g_kl);
    cudaGetSymbolAddress((void**)&vh, g_vh);
    cudaGetSymbolAddress((void**)&vl, g_vl);
    cudaGetSymbolAddress((void**)&ctx, g_ctx);

    cudaFuncSetAttribute(attn_hmma,
                         cudaFuncAttributeMaxDynamicSharedMemorySize, ATTN_SMEM);

    const int nA2 = NM * ND / 2, nW2 = ND * ND / 2;
    dim3 gg(ND / BN, NM / BM);   // (8, 32)

    // Q projection
    split_pack<<<1024, 256>>>(query, ash, asl, nA2);
    split_pack<<<512, 256>>>(Wq, bsh, bsl, nW2);
    hmma_gemm<1><<<gg, 256>>>(ash, asl, bsh, bsl, bq, nullptr, qh, ql);
    // K projection
    split_pack<<<1024, 256>>>(key_, ash, asl, nA2);
    split_pack<<<512, 256>>>(Wk, bsh, bsl, nW2);
    hmma_gemm<1><<<gg, 256>>>(ash, asl, bsh, bsl, bk, nullptr, kh, kl);
    // V projection
    split_pack<<<1024, 256>>>(value, ash, asl, nA2);
    split_pack<<<512, 256>>>(Wv, bsh, bsl, nW2);
    hmma_gemm<1><<<gg, 256>>>(ash, asl, bsh, bsl, bv, nullptr, vh, vl);

    // Attention
    attn_hmma<<<dim3(NS / 128, NH * NB), 256, ATTN_SMEM>>>();   // (16, 32)

    // Output projection
    split_pack<<<1024, 256>>>(ctx, ash, asl, nA2);
    split_pack<<<512, 256>>>(Wo, bsh, bsl, nW2);
    hmma_gemm<0><<<gg, 256>>>(ash, asl, bsh, bsl, bo, out, nullptr, nullptr);
}